// round 1
// baseline (speedup 1.0000x reference)
#include <cuda_runtime.h>
#include <math.h>
#include <float.h>

#define B_   32
#define NF_  196
#define ENC_ 2048
#define V_   32000
#define ED_  512
#define S_   32
#define H_   1024

// ---------------- scratch (single __device__ array; no allocations) ---------
static constexpr size_t SZ_K    = (size_t)B_ * NF_ * H_;          // 6,422,528
static constexpr size_t OFF_K   = 0;
static constexpr size_t OFF_V   = OFF_K + SZ_K;
static constexpr size_t OFF_MEAN= OFF_V + SZ_K;                   // B*ENC
static constexpr size_t OFF_H   = OFF_MEAN + (size_t)B_ * ENC_;
static constexpr size_t OFF_C   = OFF_H   + (size_t)B_ * H_;
static constexpr size_t OFF_HLN = OFF_C   + (size_t)B_ * H_;
static constexpr size_t OFF_Q   = OFF_HLN + (size_t)B_ * H_;
static constexpr size_t OFF_CTX = OFF_Q   + (size_t)B_ * H_;
static constexpr size_t OFF_O   = OFF_CTX + (size_t)B_ * H_;
static constexpr size_t OFF_G   = OFF_O   + (size_t)B_ * H_;      // B*4H
static constexpr size_t OFF_EMB = OFF_G   + (size_t)B_ * 4 * H_;  // B*S*ED
static constexpr size_t OFF_XP  = OFF_EMB + (size_t)B_ * S_ * ED_;// B*S*4H
static constexpr size_t OFF_AD  = OFF_XP  + (size_t)B_ * S_ * 4 * H_; // dummy attn
static constexpr size_t TOTAL_F = OFF_AD  + (size_t)B_ * S_ * NF_;

__device__ float g_scratch[TOTAL_F];

// ---------------- mean over N + exact gelu ----------------------------------
__global__ __launch_bounds__(256) void mean_gelu_kernel(
    const float* __restrict__ feat, float* __restrict__ outMean)
{
    int b = blockIdx.y;
    int e = blockIdx.x * 256 + threadIdx.x;
    const float* p = feat + (size_t)b * NF_ * ENC_ + e;
    float s = 0.f;
    #pragma unroll 4
    for (int n = 0; n < NF_; n++) s += p[(size_t)n * ENC_];
    s *= (1.0f / (float)NF_);
    outMean[(size_t)b * ENC_ + e] = 0.5f * s * (1.0f + erff(s * 0.70710678118654752f));
}

// ---------------- embedding gather -------------------------------------------
__global__ __launch_bounds__(256) void gather_kernel(
    const float* __restrict__ emb, const int* __restrict__ cap,
    float* __restrict__ out)
{
    int idx = blockIdx.x * 256 + threadIdx.x;       // < B*S*ED
    int d  = idx & (ED_ - 1);
    int bs = idx >> 9;                              // ED_=512
    out[idx] = emb[(size_t)cap[bs] * ED_ + d];
}

// ---------------- batched GEMV for M=32 skinny GEMMs -------------------------
// C[b][n] = bias[n] + add[b*add_stride+n] + sum_k A[b][k]*W[n][k]
// Grid: N/8 blocks of 256 threads; warp w handles column n = bx*8 + w.
__global__ __launch_bounds__(256) void gemvM32(
    const float* __restrict__ A,          // [32,K] contiguous
    const float* __restrict__ W,          // [N,K]
    const float* __restrict__ bias,       // [N] or null
    const float* __restrict__ add, int add_stride, // add[b*stride + n] or null
    float* __restrict__ C, int ldc,
    int K)
{
    __shared__ float sA[32][64];
    int tid = threadIdx.x, lane = tid & 31, w = tid >> 5;
    int n = blockIdx.x * 8 + w;
    const float* Wn = W + (size_t)n * K;

    float acc[32];
    #pragma unroll
    for (int b = 0; b < 32; b++) acc[b] = 0.f;

    for (int k0 = 0; k0 < K; k0 += 64) {
        __syncthreads();
        {
            int kk = tid & 63;
            int bb = tid >> 6;
            #pragma unroll
            for (int i = 0; i < 8; i++)
                sA[bb + i * 4][kk] = A[(size_t)(bb + i * 4) * K + k0 + kk];
        }
        __syncthreads();
        float w0 = Wn[k0 + lane];
        float w1 = Wn[k0 + 32 + lane];
        #pragma unroll
        for (int b = 0; b < 32; b++)
            acc[b] += w0 * sA[b][lane] + w1 * sA[b][lane + 32];
    }

    float out = 0.f;
    #pragma unroll
    for (int b = 0; b < 32; b++) {
        float v = acc[b];
        #pragma unroll
        for (int o = 16; o; o >>= 1) v += __shfl_xor_sync(0xffffffffu, v, o);
        if (lane == b) out = v;
    }
    // lane index == batch index
    float res = out;
    if (bias) res += bias[n];
    if (add)  res += add[(size_t)lane * add_stride + n];
    C[(size_t)lane * (size_t)ldc + n] = res;
}

// ---------------- tiled GEMM: C[M,N] = A[M,K] @ W[N,K]^T + bias --------------
// tile 32(M) x 128(N), 256 threads, 4x4 register blocking.
__global__ __launch_bounds__(256) void gemm_t128(
    const float* __restrict__ A, int lda,
    const float* __restrict__ W,
    const float* __restrict__ bias,
    float* __restrict__ C, int ldc,
    int K)
{
    __shared__ float sA[32][64];    // [m][k]
    __shared__ float sW[64][132];   // [k][n], 132 pad -> 528B rows (16B aligned)
    int tid = threadIdx.x;
    int tx = tid & 31, ty = tid >> 5;
    int m0 = blockIdx.y * 32;
    int n0 = blockIdx.x * 128;
    const float* Ab = A + (size_t)m0 * lda;
    const float* Wb = W + (size_t)n0 * K;

    float acc[4][4];
    #pragma unroll
    for (int i = 0; i < 4; i++)
        #pragma unroll
        for (int j = 0; j < 4; j++) acc[i][j] = 0.f;

    for (int k0 = 0; k0 < K; k0 += 64) {
        int k = tid & 63;
        int r = tid >> 6;                          // 0..3
        #pragma unroll
        for (int i = 0; i < 8; i++)
            sA[r + i * 4][k] = Ab[(size_t)(r + i * 4) * lda + k0 + k];
        #pragma unroll
        for (int i = 0; i < 32; i++)
            sW[k][r + i * 4] = Wb[(size_t)(r + i * 4) * K + k0 + k];
        __syncthreads();
        #pragma unroll
        for (int k2 = 0; k2 < 64; k2++) {
            float a0 = sA[ty * 4 + 0][k2];
            float a1 = sA[ty * 4 + 1][k2];
            float a2 = sA[ty * 4 + 2][k2];
            float a3 = sA[ty * 4 + 3][k2];
            float4 w4 = *(const float4*)&sW[k2][tx * 4];
            acc[0][0] += a0 * w4.x; acc[0][1] += a0 * w4.y; acc[0][2] += a0 * w4.z; acc[0][3] += a0 * w4.w;
            acc[1][0] += a1 * w4.x; acc[1][1] += a1 * w4.y; acc[1][2] += a1 * w4.z; acc[1][3] += a1 * w4.w;
            acc[2][0] += a2 * w4.x; acc[2][1] += a2 * w4.y; acc[2][2] += a2 * w4.z; acc[2][3] += a2 * w4.w;
            acc[3][0] += a3 * w4.x; acc[3][1] += a3 * w4.y; acc[3][2] += a3 * w4.z; acc[3][3] += a3 * w4.w;
        }
        __syncthreads();
    }

    int n = n0 + tx * 4;
    float4 bb = make_float4(0.f, 0.f, 0.f, 0.f);
    if (bias) bb = *(const float4*)(bias + n);
    #pragma unroll
    for (int i = 0; i < 4; i++) {
        size_t m = (size_t)(m0 + ty * 4 + i);
        float4 r4 = make_float4(acc[i][0] + bb.x, acc[i][1] + bb.y,
                                acc[i][2] + bb.z, acc[i][3] + bb.w);
        *(float4*)(C + m * (size_t)ldc + n) = r4;
    }
}

// ---------------- fused attention: scores -> softmax -> context --------------
// one block per batch; writes attn weights (post-softmax) and ctx.
__global__ __launch_bounds__(256) void attn_kernel(
    const float* __restrict__ q, const float* __restrict__ Kmat,
    const float* __restrict__ Vmat, float* __restrict__ ctx,
    float* __restrict__ attnw)   // base already offset by t*NF_
{
    int b = blockIdx.x;
    __shared__ float sq[H_];
    __shared__ float sp[224];
    __shared__ float red[8];
    __shared__ float bcast;
    int tid = threadIdx.x, lane = tid & 31, w = tid >> 5;

    for (int i = tid; i < H_; i += 256) sq[i] = q[b * H_ + i];
    __syncthreads();

    // scores
    for (int n = w; n < NF_; n += 8) {
        const float* kp = Kmat + ((size_t)b * NF_ + n) * H_;
        float s = 0.f;
        #pragma unroll 4
        for (int k = lane; k < H_; k += 32) s += sq[k] * kp[k];
        #pragma unroll
        for (int o = 16; o; o >>= 1) s += __shfl_xor_sync(0xffffffffu, s, o);
        if (lane == 0) sp[n] = s * 0.03125f;   // 1/sqrt(1024)
    }
    __syncthreads();

    // softmax over 196
    float v = (tid < NF_) ? sp[tid] : -FLT_MAX;
    float m = v;
    #pragma unroll
    for (int o = 16; o; o >>= 1) m = fmaxf(m, __shfl_xor_sync(0xffffffffu, m, o));
    if (lane == 0) red[w] = m;
    __syncthreads();
    if (tid == 0) {
        float mm = red[0];
        #pragma unroll
        for (int i = 1; i < 8; i++) mm = fmaxf(mm, red[i]);
        bcast = mm;
    }
    __syncthreads();
    float mx = bcast;
    float e = (tid < NF_) ? expf(v - mx) : 0.f;
    float s2 = e;
    #pragma unroll
    for (int o = 16; o; o >>= 1) s2 += __shfl_xor_sync(0xffffffffu, s2, o);
    if (lane == 0) red[w] = s2;
    __syncthreads();
    if (tid == 0) {
        float ss = 0.f;
        #pragma unroll
        for (int i = 0; i < 8; i++) ss += red[i];
        bcast = ss;
    }
    __syncthreads();
    float inv = 1.0f / bcast;
    if (tid < NF_) {
        float p = e * inv;
        sp[tid] = p;
        attnw[(size_t)b * S_ * NF_ + tid] = p;
    }
    __syncthreads();

    // context = attn @ V
    for (int h = tid; h < H_; h += 256) {
        float a = 0.f;
        #pragma unroll 4
        for (int n = 0; n < NF_; n++)
            a += sp[n] * Vmat[((size_t)b * NF_ + n) * H_ + h];
        ctx[b * H_ + h] = a;
    }
}

// ---------------- LayerNorm(h + o) -------------------------------------------
__global__ __launch_bounds__(256) void ln_kernel(
    const float* __restrict__ h, const float* __restrict__ o,
    const float* __restrict__ g, const float* __restrict__ b2,
    float* __restrict__ out)
{
    int b = blockIdx.x, tid = threadIdx.x, lane = tid & 31, w = tid >> 5;
    __shared__ float sx[H_];
    __shared__ float red[8];
    __shared__ float s_mu, s_rs;

    float loc = 0.f;
    for (int i = tid; i < H_; i += 256) {
        float x = h[b * H_ + i] + o[b * H_ + i];
        sx[i] = x;
        loc += x;
    }
    #pragma unroll
    for (int t = 16; t; t >>= 1) loc += __shfl_xor_sync(0xffffffffu, loc, t);
    if (lane == 0) red[w] = loc;
    __syncthreads();
    if (tid == 0) {
        float s = 0.f;
        #pragma unroll
        for (int i = 0; i < 8; i++) s += red[i];
        s_mu = s * (1.0f / H_);
    }
    __syncthreads();
    float mu = s_mu, loc2 = 0.f;
    for (int i = tid; i < H_; i += 256) {
        float d = sx[i] - mu;
        loc2 += d * d;
    }
    #pragma unroll
    for (int t = 16; t; t >>= 1) loc2 += __shfl_xor_sync(0xffffffffu, loc2, t);
    if (lane == 0) red[w] = loc2;
    __syncthreads();
    if (tid == 0) {
        float s = 0.f;
        #pragma unroll
        for (int i = 0; i < 8; i++) s += red[i];
        s_rs = rsqrtf(s * (1.0f / H_) + 1e-5f);
    }
    __syncthreads();
    float rs = s_rs;
    for (int i = tid; i < H_; i += 256)
        out[b * H_ + i] = (sx[i] - mu) * rs * g[i] + b2[i];
}

// ---------------- LSTM pointwise ---------------------------------------------
__global__ __launch_bounds__(256) void lstm_kernel(
    const float* __restrict__ gates, float* __restrict__ h, float* __restrict__ c)
{
    int idx = blockIdx.x * 256 + threadIdx.x;   // < B*H
    int b = idx >> 10, j = idx & (H_ - 1);
    const float* gp = gates + (size_t)b * 4 * H_;
    float ii = gp[j], ff = gp[H_ + j], gg = gp[2 * H_ + j], oo = gp[3 * H_ + j];
    float si = 1.f / (1.f + expf(-ii));
    float sf = 1.f / (1.f + expf(-ff));
    float so = 1.f / (1.f + expf(-oo));
    float cn = sf * c[idx] + si * tanhf(gg);
    float hn = so * tanhf(cn);
    c[idx] = cn;
    h[idx] = hn;
}

// ---------------- orchestration ----------------------------------------------
extern "C" void kernel_launch(void* const* d_in, const int* in_sizes, int n_in,
                              void* d_out, int out_size)
{
    const float* features = (const float*)d_in[0];
    const int*   captions = (const int*)  d_in[1];
    const float* emb      = (const float*)d_in[2];
    const float* q_w      = (const float*)d_in[3];
    const float* k_w      = (const float*)d_in[4];
    const float* v_w      = (const float*)d_in[5];
    const float* in_b     = (const float*)d_in[6];
    const float* out_w    = (const float*)d_in[7];
    const float* out_b    = (const float*)d_in[8];
    const float* h0_w     = (const float*)d_in[9];
    const float* h0_b     = (const float*)d_in[10];
    const float* c0_w     = (const float*)d_in[11];
    const float* c0_b     = (const float*)d_in[12];
    const float* w_ih     = (const float*)d_in[13];
    const float* b_ih     = (const float*)d_in[14];
    const float* w_hh     = (const float*)d_in[15];
    const float* b_hh     = (const float*)d_in[16];
    const float* ln_g     = (const float*)d_in[17];
    const float* ln_b2    = (const float*)d_in[18];
    const float* lin_w    = (const float*)d_in[19];
    const float* lin_b    = (const float*)d_in[20];

    float* sc = nullptr;
    cudaGetSymbolAddress((void**)&sc, g_scratch);
    float* gK    = sc + OFF_K;
    float* gV    = sc + OFF_V;
    float* gMean = sc + OFF_MEAN;
    float* gH    = sc + OFF_H;
    float* gC    = sc + OFF_C;
    float* gHln  = sc + OFF_HLN;
    float* gQ    = sc + OFF_Q;
    float* gCtx  = sc + OFF_CTX;
    float* gO    = sc + OFF_O;
    float* gG    = sc + OFF_G;
    float* gEmb  = sc + OFF_EMB;
    float* gXp   = sc + OFF_XP;
    float* gAd   = sc + OFF_AD;

    float* out   = (float*)d_out;
    float* preds = out;
    const size_t PRED = (size_t)B_ * S_ * V_;
    bool wa = ((size_t)out_size >= PRED + (size_t)B_ * S_ * NF_);
    float* attnb = wa ? (out + PRED) : gAd;

    // ---- setup (hoisted out of the recurrence) ----
    mean_gelu_kernel<<<dim3(ENC_ / 256, B_), 256>>>(features, gMean);
    gemvM32<<<H_ / 8, 256>>>(gMean, h0_w, h0_b, nullptr, 0, gH, H_, ENC_);
    gemvM32<<<H_ / 8, 256>>>(gMean, c0_w, c0_b, nullptr, 0, gC, H_, ENC_);
    gemm_t128<<<dim3(H_ / 128, (B_ * NF_) / 32), 256>>>(
        features, ENC_, k_w, in_b + H_,     gK, H_, ENC_);
    gemm_t128<<<dim3(H_ / 128, (B_ * NF_) / 32), 256>>>(
        features, ENC_, v_w, in_b + 2 * H_, gV, H_, ENC_);
    gather_kernel<<<(B_ * S_ * ED_) / 256, 256>>>(emb, captions, gEmb);
    gemm_t128<<<dim3((4 * H_) / 128, (B_ * S_) / 32), 256>>>(
        gEmb, ED_, w_ih, b_ih, gXp, 4 * H_, ED_);

    // ---- recurrence ----
    for (int t = 0; t < S_; t++) {
        gemvM32<<<H_ / 8, 256>>>(gH, q_w, in_b, nullptr, 0, gQ, H_, H_);
        attn_kernel<<<B_, 256>>>(gQ, gK, gV, gCtx, attnb + (size_t)t * NF_);
        gemvM32<<<H_ / 8, 256>>>(gCtx, out_w, out_b, nullptr, 0, gO, H_, H_);
        ln_kernel<<<B_, 256>>>(gH, gO, ln_g, ln_b2, gHln);
        gemvM32<<<(4 * H_) / 8, 256>>>(gHln, w_hh, b_hh,
                                       gXp + (size_t)t * 4 * H_, S_ * 4 * H_,
                                       gG, 4 * H_, H_);
        lstm_kernel<<<(B_ * H_) / 256, 256>>>(gG, gH, gC);
        gemm_t128<<<dim3(V_ / 128, 1), 256>>>(
            gH, H_, lin_w, lin_b, preds + (size_t)t * V_, S_ * V_, H_);
    }
}

// round 2
// speedup vs baseline: 1.4936x; 1.4936x over previous
#include <cuda_runtime.h>
#include <math.h>
#include <float.h>

#define B_   32
#define NF_  196
#define ENC_ 2048
#define V_   32000
#define ED_  512
#define S_   32
#define H_   1024

// ---------------- scratch (single __device__ array; no allocations) ---------
static constexpr size_t SZ_K    = (size_t)B_ * NF_ * H_;          // 6,422,528
static constexpr size_t OFF_K   = 0;
static constexpr size_t OFF_V   = OFF_K + SZ_K;
static constexpr size_t OFF_MEAN= OFF_V + SZ_K;                   // B*ENC
static constexpr size_t OFF_H   = OFF_MEAN + (size_t)B_ * ENC_;
static constexpr size_t OFF_C   = OFF_H   + (size_t)B_ * H_;
static constexpr size_t OFF_HLN = OFF_C   + (size_t)B_ * H_;
static constexpr size_t OFF_Q   = OFF_HLN + (size_t)B_ * H_;
static constexpr size_t OFF_CTX = OFF_Q   + (size_t)B_ * H_;
static constexpr size_t OFF_O   = OFF_CTX + (size_t)B_ * H_;
static constexpr size_t OFF_G   = OFF_O   + (size_t)B_ * H_;      // B*4H
static constexpr size_t OFF_EMB = OFF_G   + (size_t)B_ * 4 * H_;  // B*S*ED
static constexpr size_t OFF_XP  = OFF_EMB + (size_t)B_ * S_ * ED_;// B*S*4H
static constexpr size_t OFF_HALL= OFF_XP  + (size_t)B_ * S_ * 4 * H_; // B*S*H
static constexpr size_t OFF_AD  = OFF_HALL+ (size_t)B_ * S_ * H_;     // dummy attn
static constexpr size_t TOTAL_F = OFF_AD  + (size_t)B_ * S_ * NF_;

__device__ float g_scratch[TOTAL_F];

// ---------------- mean over N + exact gelu ----------------------------------
__global__ __launch_bounds__(256) void mean_gelu_kernel(
    const float* __restrict__ feat, float* __restrict__ outMean)
{
    int b = blockIdx.y;
    int e = blockIdx.x * 256 + threadIdx.x;
    const float* p = feat + (size_t)b * NF_ * ENC_ + e;
    float s = 0.f;
    #pragma unroll 4
    for (int n = 0; n < NF_; n++) s += p[(size_t)n * ENC_];
    s *= (1.0f / (float)NF_);
    outMean[(size_t)b * ENC_ + e] = 0.5f * s * (1.0f + erff(s * 0.70710678118654752f));
}

// ---------------- embedding gather -------------------------------------------
__global__ __launch_bounds__(256) void gather_kernel(
    const float* __restrict__ emb, const int* __restrict__ cap,
    float* __restrict__ out)
{
    int idx = blockIdx.x * 256 + threadIdx.x;       // < B*S*ED
    int d  = idx & (ED_ - 1);
    int bs = idx >> 9;                              // ED_=512
    out[idx] = emb[(size_t)cap[bs] * ED_ + d];
}

// ---------------- batched GEMV for M=32 skinny GEMMs -------------------------
// C[b][n] = bias[n] + add[b*add_stride+n] + sum_k A[b][k]*W[n][k]
__global__ __launch_bounds__(256) void gemvM32(
    const float* __restrict__ A,          // [32,K] contiguous
    const float* __restrict__ W,          // [N,K]
    const float* __restrict__ bias,       // [N] or null
    const float* __restrict__ add, int add_stride, // add[b*stride + n] or null
    float* __restrict__ C, int ldc,
    int K)
{
    __shared__ float sA[32][64];
    int tid = threadIdx.x, lane = tid & 31, w = tid >> 5;
    int n = blockIdx.x * 8 + w;
    const float* Wn = W + (size_t)n * K;

    float acc[32];
    #pragma unroll
    for (int b = 0; b < 32; b++) acc[b] = 0.f;

    for (int k0 = 0; k0 < K; k0 += 64) {
        __syncthreads();
        {
            int kk = tid & 63;
            int bb = tid >> 6;
            #pragma unroll
            for (int i = 0; i < 8; i++)
                sA[bb + i * 4][kk] = A[(size_t)(bb + i * 4) * K + k0 + kk];
        }
        __syncthreads();
        float w0 = Wn[k0 + lane];
        float w1 = Wn[k0 + 32 + lane];
        #pragma unroll
        for (int b = 0; b < 32; b++)
            acc[b] += w0 * sA[b][lane] + w1 * sA[b][lane + 32];
    }

    float out = 0.f;
    #pragma unroll
    for (int b = 0; b < 32; b++) {
        float v = acc[b];
        #pragma unroll
        for (int o = 16; o; o >>= 1) v += __shfl_xor_sync(0xffffffffu, v, o);
        if (lane == b) out = v;
    }
    float res = out;
    if (bias) res += bias[n];
    if (add)  res += add[(size_t)lane * add_stride + n];
    C[(size_t)lane * (size_t)ldc + n] = res;
}

// ---------------- tiled GEMM: C[M,N] = A[M,K] @ W[N,K]^T + bias --------------
// 64x64 tile, BK=32, 256 threads, 4x4 register blocking.
// Both smem tiles k-major with row pad 68 floats (272B, 16B aligned):
// inner loop = 2 conflict-free LDS.128 + 16 FFMA per k.
__global__ __launch_bounds__(256) void gemm64(
    const float* __restrict__ A, int lda,
    const float* __restrict__ W,          // [N,K], ld = K
    const float* __restrict__ bias,
    float* __restrict__ C, int ldc,
    int K)
{
    __shared__ float sA[32][68];
    __shared__ float sW[32][68];
    int tid = threadIdx.x;
    int tx = tid & 15, ty = tid >> 4;     // tx -> n quad, ty -> m quad
    int m0 = blockIdx.y * 64, n0 = blockIdx.x * 64;
    const float* Ab = A + (size_t)m0 * lda;
    const float* Wb = W + (size_t)n0 * K;

    int r0 = tid >> 3;                    // 0..31 (row within half-tile)
    int c0 = (tid & 7) * 4;               // k offset (float4) within 32-chunk

    float acc[4][4];
    #pragma unroll
    for (int i = 0; i < 4; i++)
        #pragma unroll
        for (int j = 0; j < 4; j++) acc[i][j] = 0.f;

    for (int k0 = 0; k0 < K; k0 += 32) {
        float4 a0 = *(const float4*)(Ab + (size_t)r0 * lda + k0 + c0);
        float4 a1 = *(const float4*)(Ab + (size_t)(r0 + 32) * lda + k0 + c0);
        float4 w0 = *(const float4*)(Wb + (size_t)r0 * K + k0 + c0);
        float4 w1 = *(const float4*)(Wb + (size_t)(r0 + 32) * K + k0 + c0);
        __syncthreads();
        // transpose into k-major smem
        sA[c0 + 0][r0] = a0.x; sA[c0 + 1][r0] = a0.y; sA[c0 + 2][r0] = a0.z; sA[c0 + 3][r0] = a0.w;
        sA[c0 + 0][r0 + 32] = a1.x; sA[c0 + 1][r0 + 32] = a1.y; sA[c0 + 2][r0 + 32] = a1.z; sA[c0 + 3][r0 + 32] = a1.w;
        sW[c0 + 0][r0] = w0.x; sW[c0 + 1][r0] = w0.y; sW[c0 + 2][r0] = w0.z; sW[c0 + 3][r0] = w0.w;
        sW[c0 + 0][r0 + 32] = w1.x; sW[c0 + 1][r0 + 32] = w1.y; sW[c0 + 2][r0 + 32] = w1.z; sW[c0 + 3][r0 + 32] = w1.w;
        __syncthreads();
        #pragma unroll
        for (int k2 = 0; k2 < 32; k2++) {
            float4 a4 = *(const float4*)&sA[k2][ty * 4];
            float4 b4 = *(const float4*)&sW[k2][tx * 4];
            acc[0][0] += a4.x * b4.x; acc[0][1] += a4.x * b4.y; acc[0][2] += a4.x * b4.z; acc[0][3] += a4.x * b4.w;
            acc[1][0] += a4.y * b4.x; acc[1][1] += a4.y * b4.y; acc[1][2] += a4.y * b4.z; acc[1][3] += a4.y * b4.w;
            acc[2][0] += a4.z * b4.x; acc[2][1] += a4.z * b4.y; acc[2][2] += a4.z * b4.z; acc[2][3] += a4.z * b4.w;
            acc[3][0] += a4.w * b4.x; acc[3][1] += a4.w * b4.y; acc[3][2] += a4.w * b4.z; acc[3][3] += a4.w * b4.w;
        }
    }

    int n = n0 + tx * 4;
    float4 bb = make_float4(0.f, 0.f, 0.f, 0.f);
    if (bias) bb = *(const float4*)(bias + n);
    #pragma unroll
    for (int i = 0; i < 4; i++) {
        size_t m = (size_t)(m0 + ty * 4 + i);
        float4 r4 = make_float4(acc[i][0] + bb.x, acc[i][1] + bb.y,
                                acc[i][2] + bb.z, acc[i][3] + bb.w);
        *(float4*)(C + m * (size_t)ldc + n) = r4;
    }
}

// ---------------- fused attention: scores -> softmax -> context --------------
__global__ __launch_bounds__(256) void attn_kernel(
    const float* __restrict__ q, const float* __restrict__ Kmat,
    const float* __restrict__ Vmat, float* __restrict__ ctx,
    float* __restrict__ attnw)   // base already offset by t*NF_
{
    int b = blockIdx.x;
    __shared__ float sq[H_];
    __shared__ float sp[224];
    __shared__ float red[8];
    __shared__ float bcast;
    int tid = threadIdx.x, lane = tid & 31, w = tid >> 5;

    for (int i = tid; i < H_; i += 256) sq[i] = q[b * H_ + i];
    __syncthreads();

    for (int n = w; n < NF_; n += 8) {
        const float* kp = Kmat + ((size_t)b * NF_ + n) * H_;
        float s = 0.f;
        #pragma unroll 4
        for (int k = lane; k < H_; k += 32) s += sq[k] * kp[k];
        #pragma unroll
        for (int o = 16; o; o >>= 1) s += __shfl_xor_sync(0xffffffffu, s, o);
        if (lane == 0) sp[n] = s * 0.03125f;   // 1/sqrt(1024)
    }
    __syncthreads();

    float v = (tid < NF_) ? sp[tid] : -FLT_MAX;
    float m = v;
    #pragma unroll
    for (int o = 16; o; o >>= 1) m = fmaxf(m, __shfl_xor_sync(0xffffffffu, m, o));
    if (lane == 0) red[w] = m;
    __syncthreads();
    if (tid == 0) {
        float mm = red[0];
        #pragma unroll
        for (int i = 1; i < 8; i++) mm = fmaxf(mm, red[i]);
        bcast = mm;
    }
    __syncthreads();
    float mx = bcast;
    float e = (tid < NF_) ? expf(v - mx) : 0.f;
    float s2 = e;
    #pragma unroll
    for (int o = 16; o; o >>= 1) s2 += __shfl_xor_sync(0xffffffffu, s2, o);
    if (lane == 0) red[w] = s2;
    __syncthreads();
    if (tid == 0) {
        float ss = 0.f;
        #pragma unroll
        for (int i = 0; i < 8; i++) ss += red[i];
        bcast = ss;
    }
    __syncthreads();
    float inv = 1.0f / bcast;
    if (tid < NF_) {
        float p = e * inv;
        sp[tid] = p;
        attnw[(size_t)b * S_ * NF_ + tid] = p;
    }
    __syncthreads();

    for (int h = tid; h < H_; h += 256) {
        float a = 0.f;
        #pragma unroll 4
        for (int n = 0; n < NF_; n++)
            a += sp[n] * Vmat[((size_t)b * NF_ + n) * H_ + h];
        ctx[b * H_ + h] = a;
    }
}

// ---------------- LayerNorm(h + o) -------------------------------------------
__global__ __launch_bounds__(256) void ln_kernel(
    const float* __restrict__ h, const float* __restrict__ o,
    const float* __restrict__ g, const float* __restrict__ b2,
    float* __restrict__ out)
{
    int b = blockIdx.x, tid = threadIdx.x, lane = tid & 31, w = tid >> 5;
    __shared__ float sx[H_];
    __shared__ float red[8];
    __shared__ float s_mu, s_rs;

    float loc = 0.f;
    for (int i = tid; i < H_; i += 256) {
        float x = h[b * H_ + i] + o[b * H_ + i];
        sx[i] = x;
        loc += x;
    }
    #pragma unroll
    for (int t = 16; t; t >>= 1) loc += __shfl_xor_sync(0xffffffffu, loc, t);
    if (lane == 0) red[w] = loc;
    __syncthreads();
    if (tid == 0) {
        float s = 0.f;
        #pragma unroll
        for (int i = 0; i < 8; i++) s += red[i];
        s_mu = s * (1.0f / H_);
    }
    __syncthreads();
    float mu = s_mu, loc2 = 0.f;
    for (int i = tid; i < H_; i += 256) {
        float d = sx[i] - mu;
        loc2 += d * d;
    }
    #pragma unroll
    for (int t = 16; t; t >>= 1) loc2 += __shfl_xor_sync(0xffffffffu, loc2, t);
    if (lane == 0) red[w] = loc2;
    __syncthreads();
    if (tid == 0) {
        float s = 0.f;
        #pragma unroll
        for (int i = 0; i < 8; i++) s += red[i];
        s_rs = rsqrtf(s * (1.0f / H_) + 1e-5f);
    }
    __syncthreads();
    float rs = s_rs;
    for (int i = tid; i < H_; i += 256)
        out[b * H_ + i] = (sx[i] - mu) * rs * g[i] + b2[i];
}

// ---------------- LSTM pointwise (also records h into gHall[b][t]) -----------
__global__ __launch_bounds__(256) void lstm_kernel(
    const float* __restrict__ gates, float* __restrict__ h, float* __restrict__ c,
    float* __restrict__ hall, int t)
{
    int idx = blockIdx.x * 256 + threadIdx.x;   // < B*H
    int b = idx >> 10, j = idx & (H_ - 1);
    const float* gp = gates + (size_t)b * 4 * H_;
    float ii = gp[j], ff = gp[H_ + j], gg = gp[2 * H_ + j], oo = gp[3 * H_ + j];
    float si = 1.f / (1.f + expf(-ii));
    float sf = 1.f / (1.f + expf(-ff));
    float so = 1.f / (1.f + expf(-oo));
    float cn = sf * c[idx] + si * tanhf(gg);
    float hn = so * tanhf(cn);
    c[idx] = cn;
    h[idx] = hn;
    hall[((size_t)b * S_ + t) * H_ + j] = hn;
}

// ---------------- orchestration ----------------------------------------------
extern "C" void kernel_launch(void* const* d_in, const int* in_sizes, int n_in,
                              void* d_out, int out_size)
{
    const float* features = (const float*)d_in[0];
    const int*   captions = (const int*)  d_in[1];
    const float* emb      = (const float*)d_in[2];
    const float* q_w      = (const float*)d_in[3];
    const float* k_w      = (const float*)d_in[4];
    const float* v_w      = (const float*)d_in[5];
    const float* in_b     = (const float*)d_in[6];
    const float* out_w    = (const float*)d_in[7];
    const float* out_b    = (const float*)d_in[8];
    const float* h0_w     = (const float*)d_in[9];
    const float* h0_b     = (const float*)d_in[10];
    const float* c0_w     = (const float*)d_in[11];
    const float* c0_b     = (const float*)d_in[12];
    const float* w_ih     = (const float*)d_in[13];
    const float* b_ih     = (const float*)d_in[14];
    const float* w_hh     = (const float*)d_in[15];
    const float* b_hh     = (const float*)d_in[16];
    const float* ln_g     = (const float*)d_in[17];
    const float* ln_b2    = (const float*)d_in[18];
    const float* lin_w    = (const float*)d_in[19];
    const float* lin_b    = (const float*)d_in[20];

    float* sc = nullptr;
    cudaGetSymbolAddress((void**)&sc, g_scratch);
    float* gK    = sc + OFF_K;
    float* gV    = sc + OFF_V;
    float* gMean = sc + OFF_MEAN;
    float* gH    = sc + OFF_H;
    float* gC    = sc + OFF_C;
    float* gHln  = sc + OFF_HLN;
    float* gQ    = sc + OFF_Q;
    float* gCtx  = sc + OFF_CTX;
    float* gO    = sc + OFF_O;
    float* gG    = sc + OFF_G;
    float* gEmb  = sc + OFF_EMB;
    float* gXp   = sc + OFF_XP;
    float* gHall = sc + OFF_HALL;
    float* gAd   = sc + OFF_AD;

    float* out   = (float*)d_out;
    float* preds = out;
    const size_t PRED = (size_t)B_ * S_ * V_;
    bool wa = ((size_t)out_size >= PRED + (size_t)B_ * S_ * NF_);
    float* attnb = wa ? (out + PRED) : gAd;

    // ---- setup (hoisted out of the recurrence) ----
    mean_gelu_kernel<<<dim3(ENC_ / 256, B_), 256>>>(features, gMean);
    gemvM32<<<H_ / 8, 256>>>(gMean, h0_w, h0_b, nullptr, 0, gH, H_, ENC_);
    gemvM32<<<H_ / 8, 256>>>(gMean, c0_w, c0_b, nullptr, 0, gC, H_, ENC_);
    gemm64<<<dim3(H_ / 64, (B_ * NF_) / 64), 256>>>(
        features, ENC_, k_w, in_b + H_,     gK, H_, ENC_);
    gemm64<<<dim3(H_ / 64, (B_ * NF_) / 64), 256>>>(
        features, ENC_, v_w, in_b + 2 * H_, gV, H_, ENC_);
    gather_kernel<<<(B_ * S_ * ED_) / 256, 256>>>(emb, captions, gEmb);
    gemm64<<<dim3((4 * H_) / 64, (B_ * S_) / 64), 256>>>(
        gEmb, ED_, w_ih, b_ih, gXp, 4 * H_, ED_);

    // ---- recurrence (logits hoisted out) ----
    for (int t = 0; t < S_; t++) {
        gemvM32<<<H_ / 8, 256>>>(gH, q_w, in_b, nullptr, 0, gQ, H_, H_);
        attn_kernel<<<B_, 256>>>(gQ, gK, gV, gCtx, attnb + (size_t)t * NF_);
        gemvM32<<<H_ / 8, 256>>>(gCtx, out_w, out_b, nullptr, 0, gO, H_, H_);
        ln_kernel<<<B_, 256>>>(gH, gO, ln_g, ln_b2, gHln);
        gemvM32<<<(4 * H_) / 8, 256>>>(gHln, w_hh, b_hh,
                                       gXp + (size_t)t * 4 * H_, S_ * 4 * H_,
                                       gG, 4 * H_, H_);
        lstm_kernel<<<(B_ * H_) / 256, 256>>>(gG, gH, gC, gHall, t);
    }

    // ---- batched logits: [B*S, V] = gHall @ lin_w^T + lin_b ----
    gemm64<<<dim3(V_ / 64, (B_ * S_) / 64), 256>>>(
        gHall, H_, lin_w, lin_b, preds, V_, H_);
}

// round 3
// speedup vs baseline: 2.3381x; 1.5655x over previous
#include <cuda_runtime.h>
#include <math.h>
#include <float.h>

#define B_   32
#define NF_  196
#define ENC_ 2048
#define V_   32000
#define ED_  512
#define S_   32
#define H_   1024
#define NB_  128        // persistent grid size (all co-resident on 148 SMs)

// ---------------- scratch (single __device__ array; no allocations) ---------
static constexpr size_t SZ_K    = (size_t)B_ * NF_ * H_;
static constexpr size_t OFF_K   = 0;
static constexpr size_t OFF_V   = OFF_K + SZ_K;
static constexpr size_t OFF_MEAN= OFF_V + SZ_K;
static constexpr size_t OFF_H   = OFF_MEAN + (size_t)B_ * ENC_;
static constexpr size_t OFF_C   = OFF_H   + (size_t)B_ * H_;
static constexpr size_t OFF_HLN = OFF_C   + (size_t)B_ * H_;
static constexpr size_t OFF_Q   = OFF_HLN + (size_t)B_ * H_;
static constexpr size_t OFF_CTX = OFF_Q   + (size_t)B_ * H_;
static constexpr size_t OFF_O   = OFF_CTX + (size_t)B_ * H_;
static constexpr size_t OFF_SC  = OFF_O   + (size_t)B_ * H_;      // 32*256 scores
static constexpr size_t OFF_EMB = OFF_SC  + (size_t)B_ * 256;
static constexpr size_t OFF_XP  = OFF_EMB + (size_t)B_ * S_ * ED_;
static constexpr size_t OFF_HALL= OFF_XP  + (size_t)B_ * S_ * 4 * H_;
static constexpr size_t OFF_AD  = OFF_HALL+ (size_t)B_ * S_ * H_;
static constexpr size_t TOTAL_F = OFF_AD  + (size_t)B_ * S_ * NF_;

__device__ float g_scratch[TOTAL_F];
__device__ unsigned g_bar_count = 0;
__device__ unsigned g_bar_gen   = 0;

// ---------------- grid-wide barrier (all NB_ blocks resident) ----------------
__device__ __forceinline__ void grid_bar() {
    __syncthreads();
    if (threadIdx.x == 0) {
        __threadfence();
        unsigned gen = *(volatile unsigned*)&g_bar_gen;
        unsigned a = atomicAdd(&g_bar_count, 1u);
        if (a == NB_ - 1) {
            atomicExch(&g_bar_count, 0u);
            __threadfence();
            atomicAdd(&g_bar_gen, 1u);
        } else {
            while (*(volatile unsigned*)&g_bar_gen == gen) { }
        }
        __threadfence();
    }
    __syncthreads();
}

// ---------------- mean over N + exact gelu ----------------------------------
__global__ __launch_bounds__(256) void mean_gelu_kernel(
    const float* __restrict__ feat, float* __restrict__ outMean)
{
    int b = blockIdx.y;
    int e = blockIdx.x * 256 + threadIdx.x;
    const float* p = feat + (size_t)b * NF_ * ENC_ + e;
    float s = 0.f;
    #pragma unroll 4
    for (int n = 0; n < NF_; n++) s += p[(size_t)n * ENC_];
    s *= (1.0f / (float)NF_);
    outMean[(size_t)b * ENC_ + e] = 0.5f * s * (1.0f + erff(s * 0.70710678118654752f));
}

// ---------------- embedding gather -------------------------------------------
__global__ __launch_bounds__(256) void gather_kernel(
    const float* __restrict__ emb, const int* __restrict__ cap,
    float* __restrict__ out)
{
    int idx = blockIdx.x * 256 + threadIdx.x;
    int d  = idx & (ED_ - 1);
    int bs = idx >> 9;
    out[idx] = emb[(size_t)cap[bs] * ED_ + d];
}

// ---------------- batched GEMV for M=32 skinny (setup h0/c0 only) -----------
__global__ __launch_bounds__(256) void gemvM32(
    const float* __restrict__ A, const float* __restrict__ W,
    const float* __restrict__ bias, float* __restrict__ C, int ldc, int K)
{
    __shared__ float sA[32][64];
    int tid = threadIdx.x, lane = tid & 31, w = tid >> 5;
    int n = blockIdx.x * 8 + w;
    const float* Wn = W + (size_t)n * K;
    float acc[32];
    #pragma unroll
    for (int b = 0; b < 32; b++) acc[b] = 0.f;
    for (int k0 = 0; k0 < K; k0 += 64) {
        __syncthreads();
        int kk = tid & 63, bb = tid >> 6;
        #pragma unroll
        for (int i = 0; i < 8; i++)
            sA[bb + i * 4][kk] = A[(size_t)(bb + i * 4) * K + k0 + kk];
        __syncthreads();
        float w0 = Wn[k0 + lane], w1 = Wn[k0 + 32 + lane];
        #pragma unroll
        for (int b = 0; b < 32; b++)
            acc[b] += w0 * sA[b][lane] + w1 * sA[b][lane + 32];
    }
    float out = 0.f;
    #pragma unroll
    for (int b = 0; b < 32; b++) {
        float v = acc[b];
        #pragma unroll
        for (int o = 16; o; o >>= 1) v += __shfl_xor_sync(0xffffffffu, v, o);
        if (lane == b) out = v;
    }
    C[(size_t)lane * (size_t)ldc + n] = out + bias[n];
}

// ---------------- 128x128 SGEMM: C = A @ W^T + bias --------------------------
__global__ __launch_bounds__(256, 2) void gemm128(
    const float* __restrict__ A, int lda,
    const float* __restrict__ W,          // [N,K]
    const float* __restrict__ bias,
    float* __restrict__ C, int ldc, int K)
{
    __shared__ float sA[16][132];
    __shared__ float sB[16][132];
    int tid = threadIdx.x;
    int m0 = blockIdx.y * 128, n0 = blockIdx.x * 128;
    int lr = tid >> 2;                 // 0..63
    int lk = (tid & 3) * 4;            // 0,4,8,12
    const float* Ab = A + (size_t)m0 * lda + lk;
    const float* Wb = W + (size_t)n0 * K + lk;
    int tx = tid & 15, ty = tid >> 4;

    float acc[8][8];
    #pragma unroll
    for (int i = 0; i < 8; i++)
        #pragma unroll
        for (int j = 0; j < 8; j++) acc[i][j] = 0.f;

    for (int k0 = 0; k0 < K; k0 += 16) {
        float4 a0 = *(const float4*)(Ab + (size_t)lr * lda + k0);
        float4 a1 = *(const float4*)(Ab + (size_t)(lr + 64) * lda + k0);
        float4 b0 = *(const float4*)(Wb + (size_t)lr * K + k0);
        float4 b1 = *(const float4*)(Wb + (size_t)(lr + 64) * K + k0);
        __syncthreads();
        sA[lk+0][lr]=a0.x; sA[lk+1][lr]=a0.y; sA[lk+2][lr]=a0.z; sA[lk+3][lr]=a0.w;
        sA[lk+0][lr+64]=a1.x; sA[lk+1][lr+64]=a1.y; sA[lk+2][lr+64]=a1.z; sA[lk+3][lr+64]=a1.w;
        sB[lk+0][lr]=b0.x; sB[lk+1][lr]=b0.y; sB[lk+2][lr]=b0.z; sB[lk+3][lr]=b0.w;
        sB[lk+0][lr+64]=b1.x; sB[lk+1][lr+64]=b1.y; sB[lk+2][lr+64]=b1.z; sB[lk+3][lr+64]=b1.w;
        __syncthreads();
        #pragma unroll
        for (int k = 0; k < 16; k++) {
            float ar[8], br[8];
            *(float4*)&ar[0] = *(const float4*)&sA[k][ty * 8];
            *(float4*)&ar[4] = *(const float4*)&sA[k][ty * 8 + 4];
            *(float4*)&br[0] = *(const float4*)&sB[k][tx * 8];
            *(float4*)&br[4] = *(const float4*)&sB[k][tx * 8 + 4];
            #pragma unroll
            for (int i = 0; i < 8; i++)
                #pragma unroll
                for (int j = 0; j < 8; j++)
                    acc[i][j] += ar[i] * br[j];
        }
    }

    int n = n0 + tx * 8;
    float bb[8] = {0.f,0.f,0.f,0.f,0.f,0.f,0.f,0.f};
    if (bias) {
        *(float4*)&bb[0] = *(const float4*)(bias + n);
        *(float4*)&bb[4] = *(const float4*)(bias + n + 4);
    }
    #pragma unroll
    for (int i = 0; i < 8; i++) {
        size_t m = (size_t)(m0 + ty * 8 + i);
        float4 r0 = make_float4(acc[i][0]+bb[0], acc[i][1]+bb[1], acc[i][2]+bb[2], acc[i][3]+bb[3]);
        float4 r1 = make_float4(acc[i][4]+bb[4], acc[i][5]+bb[5], acc[i][6]+bb[6], acc[i][7]+bb[7]);
        *(float4*)(C + m * (size_t)ldc + n)     = r0;
        *(float4*)(C + m * (size_t)ldc + n + 4) = r1;
    }
}

// ---------------- in-kernel gemv phase (M=32, 8 cols/block) ------------------
__device__ __forceinline__ void gemv_phase(
    const float* __restrict__ A, const float* __restrict__ W,
    const float* __restrict__ bias, float* __restrict__ C,
    float* SB, int bx, int tid)
{
    int lane = tid & 31, w = tid >> 5;
    int n = bx * 8 + w;
    const float* Wn = W + (size_t)n * H_;
    float acc[32];
    #pragma unroll
    for (int b = 0; b < 32; b++) acc[b] = 0.f;
    for (int k0 = 0; k0 < H_; k0 += 64) {
        __syncthreads();
        int kk = tid & 63, bb = tid >> 6;
        #pragma unroll
        for (int i = 0; i < 8; i++)
            SB[(bb + i * 4) * 64 + kk] = A[(size_t)(bb + i * 4) * H_ + k0 + kk];
        __syncthreads();
        float w0 = Wn[k0 + lane], w1 = Wn[k0 + 32 + lane];
        #pragma unroll
        for (int b = 0; b < 32; b++)
            acc[b] += w0 * SB[b * 64 + lane] + w1 * SB[b * 64 + lane + 32];
    }
    float out = 0.f;
    #pragma unroll
    for (int b = 0; b < 32; b++) {
        float v = acc[b];
        #pragma unroll
        for (int o = 16; o; o >>= 1) v += __shfl_xor_sync(0xffffffffu, v, o);
        if (lane == b) out = v;
    }
    C[(size_t)lane * H_ + n] = out + bias[n];
}

// ---------------- persistent recurrence kernel -------------------------------
__global__ __launch_bounds__(256, 1) void recurrence_kernel(
    const float* __restrict__ q_w,  const float* __restrict__ in_b,
    const float* __restrict__ out_w,const float* __restrict__ out_b,
    const float* __restrict__ w_hh, const float* __restrict__ b_hh,
    const float* __restrict__ ln_g, const float* __restrict__ ln_b2,
    const float* __restrict__ gK,   const float* __restrict__ gV,
    const float* __restrict__ gXp,
    float* gH, float* gC, float* gHln, float* gQ, float* gSc,
    float* gCtx, float* gO, float* gHall, float* attnb)
{
    __shared__ float SB[3072];
    __shared__ float sred[8];
    __shared__ float sbc;
    int tid = threadIdx.x, lane = tid & 31, w = tid >> 5;
    int bx = blockIdx.x;

    for (int t = 0; t < S_; t++) {
        // ---- P0: q = h @ q_w^T + in_b[:H] ----
        gemv_phase(gH, q_w, in_b, gQ, SB, bx, tid);
        grid_bar();

        // ---- P1: scores[b][n] = (q[b]·K[b][n]) / 32 ----
        {
            int b = bx >> 2, part = bx & 3;
            for (int i = tid; i < H_; i += 256) SB[i] = gQ[b * H_ + i];
            __syncthreads();
            for (int n = part * 49 + w; n < part * 49 + 49; n += 8) {
                const float* kp = gK + ((size_t)b * NF_ + n) * H_;
                float s = 0.f;
                #pragma unroll 4
                for (int k = lane; k < H_; k += 32) s += SB[k] * kp[k];
                #pragma unroll
                for (int o = 16; o; o >>= 1) s += __shfl_xor_sync(0xffffffffu, s, o);
                if (lane == 0) gSc[b * 256 + n] = s * 0.03125f;
            }
        }
        grid_bar();

        // ---- P2: softmax + ctx ----
        {
            int b = bx >> 2, part = bx & 3;
            float v = (tid < NF_) ? gSc[b * 256 + tid] : -FLT_MAX;
            float m = v;
            #pragma unroll
            for (int o = 16; o; o >>= 1) m = fmaxf(m, __shfl_xor_sync(0xffffffffu, m, o));
            if (lane == 0) sred[w] = m;
            __syncthreads();
            if (tid == 0) {
                float mm = sred[0];
                #pragma unroll
                for (int i = 1; i < 8; i++) mm = fmaxf(mm, sred[i]);
                sbc = mm;
            }
            __syncthreads();
            float mx = sbc;
            float e = (tid < NF_) ? expf(v - mx) : 0.f;
            float s2 = e;
            #pragma unroll
            for (int o = 16; o; o >>= 1) s2 += __shfl_xor_sync(0xffffffffu, s2, o);
            if (lane == 0) sred[w] = s2;
            __syncthreads();
            if (tid == 0) {
                float ss = 0.f;
                #pragma unroll
                for (int i = 0; i < 8; i++) ss += sred[i];
                sbc = ss;
            }
            __syncthreads();
            float p = e / sbc;
            if (tid < NF_) {
                SB[tid] = p;
                if (part == 0) attnb[((size_t)b * S_ + t) * NF_ + tid] = p;
            }
            __syncthreads();
            int h = part * 256 + tid;
            const float* vb = gV + (size_t)b * NF_ * H_ + h;
            float a = 0.f;
            #pragma unroll 4
            for (int n = 0; n < NF_; n++) a += SB[n] * vb[(size_t)n * H_];
            gCtx[b * H_ + h] = a;
        }
        grid_bar();

        // ---- P3: o = ctx @ out_w^T + out_b ----
        gemv_phase(gCtx, out_w, out_b, gO, SB, bx, tid);
        grid_bar();

        // ---- P4: hln = LN(h + o) (32 active blocks) ----
        if (bx < 32) {
            int b = bx;
            float loc = 0.f;
            for (int i = tid; i < H_; i += 256) {
                float x = gH[b * H_ + i] + gO[b * H_ + i];
                SB[i] = x;
                loc += x;
            }
            #pragma unroll
            for (int o = 16; o; o >>= 1) loc += __shfl_xor_sync(0xffffffffu, loc, o);
            if (lane == 0) sred[w] = loc;
            __syncthreads();
            if (tid == 0) {
                float s = 0.f;
                #pragma unroll
                for (int i = 0; i < 8; i++) s += sred[i];
                sbc = s * (1.0f / H_);
            }
            __syncthreads();
            float mu = sbc, loc2 = 0.f;
            for (int i = tid; i < H_; i += 256) {
                float d = SB[i] - mu;
                loc2 += d * d;
            }
            #pragma unroll
            for (int o = 16; o; o >>= 1) loc2 += __shfl_xor_sync(0xffffffffu, loc2, o);
            if (lane == 0) sred[w] = loc2;
            __syncthreads();
            if (tid == 0) {
                float s = 0.f;
                #pragma unroll
                for (int i = 0; i < 8; i++) s += sred[i];
                sbc = rsqrtf(s * (1.0f / H_) + 1e-5f);
            }
            __syncthreads();
            float rs = sbc;
            for (int i = tid; i < H_; i += 256)
                gHln[b * H_ + i] = (SB[i] - mu) * rs * ln_g[i] + ln_b2[i];
        }
        grid_bar();

        // ---- P5: gates (4 x 1024 cols) + LSTM pointwise ----
        {
            int j = bx * 8 + w;
            for (int gp = 0; gp < 4; gp += 2) {
                const float* W0 = w_hh + (size_t)(gp * H_ + j) * H_;
                const float* W1 = w_hh + (size_t)((gp + 1) * H_ + j) * H_;
                float accA[32], accB[32];
                #pragma unroll
                for (int b = 0; b < 32; b++) { accA[b] = 0.f; accB[b] = 0.f; }
                for (int k0 = 0; k0 < H_; k0 += 64) {
                    __syncthreads();
                    int kk = tid & 63, bb = tid >> 6;
                    #pragma unroll
                    for (int i = 0; i < 8; i++)
                        SB[(bb + i * 4) * 64 + kk] = gHln[(size_t)(bb + i * 4) * H_ + k0 + kk];
                    __syncthreads();
                    float wa0 = W0[k0 + lane], wa1 = W0[k0 + 32 + lane];
                    float wb0 = W1[k0 + lane], wb1 = W1[k0 + 32 + lane];
                    #pragma unroll
                    for (int b = 0; b < 32; b++) {
                        float x0 = SB[b * 64 + lane], x1 = SB[b * 64 + lane + 32];
                        accA[b] += wa0 * x0 + wa1 * x1;
                        accB[b] += wb0 * x0 + wb1 * x1;
                    }
                }
                float outA = 0.f, outB = 0.f;
                #pragma unroll
                for (int b = 0; b < 32; b++) {
                    float vA = accA[b], vB = accB[b];
                    #pragma unroll
                    for (int o = 16; o; o >>= 1) {
                        vA += __shfl_xor_sync(0xffffffffu, vA, o);
                        vB += __shfl_xor_sync(0xffffffffu, vB, o);
                    }
                    if (lane == b) { outA = vA; outB = vB; }
                }
                int nA = gp * H_ + j, nB = (gp + 1) * H_ + j;
                size_t xrow = ((size_t)lane * S_ + t) * (4 * H_);
                outA += b_hh[nA] + gXp[xrow + nA];
                outB += b_hh[nB] + gXp[xrow + nB];
                SB[2048 + gp * 256 + w * 32 + lane] = outA;
                SB[2048 + (gp + 1) * 256 + w * 32 + lane] = outB;
            }
            __syncthreads();
            int b = tid & 31, jj = tid >> 5;
            int j2 = bx * 8 + jj;
            float ii = SB[2048 + 0 * 256 + jj * 32 + b];
            float ff = SB[2048 + 1 * 256 + jj * 32 + b];
            float gg = SB[2048 + 2 * 256 + jj * 32 + b];
            float oo = SB[2048 + 3 * 256 + jj * 32 + b];
            float si = 1.f / (1.f + expf(-ii));
            float sf = 1.f / (1.f + expf(-ff));
            float so = 1.f / (1.f + expf(-oo));
            float cn = sf * gC[b * H_ + j2] + si * tanhf(gg);
            float hn = so * tanhf(cn);
            gC[b * H_ + j2] = cn;
            gH[b * H_ + j2] = hn;
            gHall[((size_t)b * S_ + t) * H_ + j2] = hn;
        }
        grid_bar();
    }
}

// ---------------- orchestration ----------------------------------------------
extern "C" void kernel_launch(void* const* d_in, const int* in_sizes, int n_in,
                              void* d_out, int out_size)
{
    const float* features = (const float*)d_in[0];
    const int*   captions = (const int*)  d_in[1];
    const float* emb      = (const float*)d_in[2];
    const float* q_w      = (const float*)d_in[3];
    const float* k_w      = (const float*)d_in[4];
    const float* v_w      = (const float*)d_in[5];
    const float* in_b     = (const float*)d_in[6];
    const float* out_w    = (const float*)d_in[7];
    const float* out_b    = (const float*)d_in[8];
    const float* h0_w     = (const float*)d_in[9];
    const float* h0_b     = (const float*)d_in[10];
    const float* c0_w     = (const float*)d_in[11];
    const float* c0_b     = (const float*)d_in[12];
    const float* w_ih     = (const float*)d_in[13];
    const float* b_ih     = (const float*)d_in[14];
    const float* w_hh     = (const float*)d_in[15];
    const float* b_hh     = (const float*)d_in[16];
    const float* ln_g     = (const float*)d_in[17];
    const float* ln_b2    = (const float*)d_in[18];
    const float* lin_w    = (const float*)d_in[19];
    const float* lin_b    = (const float*)d_in[20];

    float* sc = nullptr;
    cudaGetSymbolAddress((void**)&sc, g_scratch);
    float* gK    = sc + OFF_K;
    float* gV    = sc + OFF_V;
    float* gMean = sc + OFF_MEAN;
    float* gH    = sc + OFF_H;
    float* gC    = sc + OFF_C;
    float* gHln  = sc + OFF_HLN;
    float* gQ    = sc + OFF_Q;
    float* gCtx  = sc + OFF_CTX;
    float* gO    = sc + OFF_O;
    float* gSc   = sc + OFF_SC;
    float* gEmb  = sc + OFF_EMB;
    float* gXp   = sc + OFF_XP;
    float* gHall = sc + OFF_HALL;
    float* gAd   = sc + OFF_AD;

    float* out   = (float*)d_out;
    float* preds = out;
    const size_t PRED = (size_t)B_ * S_ * V_;
    bool wa = ((size_t)out_size >= PRED + (size_t)B_ * S_ * NF_);
    float* attnb = wa ? (out + PRED) : gAd;

    // ---- setup (hoisted out of the recurrence) ----
    mean_gelu_kernel<<<dim3(ENC_ / 256, B_), 256>>>(features, gMean);
    gemvM32<<<H_ / 8, 256>>>(gMean, h0_w, h0_b, gH, H_, ENC_);
    gemvM32<<<H_ / 8, 256>>>(gMean, c0_w, c0_b, gC, H_, ENC_);
    gemm128<<<dim3(H_ / 128, (B_ * NF_) / 128), 256>>>(
        features, ENC_, k_w, in_b + H_,     gK, H_, ENC_);
    gemm128<<<dim3(H_ / 128, (B_ * NF_) / 128), 256>>>(
        features, ENC_, v_w, in_b + 2 * H_, gV, H_, ENC_);
    gather_kernel<<<(B_ * S_ * ED_) / 256, 256>>>(emb, captions, gEmb);
    gemm128<<<dim3((4 * H_) / 128, (B_ * S_) / 128), 256>>>(
        gEmb, ED_, w_ih, b_ih, gXp, 4 * H_, ED_);

    // ---- whole recurrence in one persistent kernel ----
    recurrence_kernel<<<NB_, 256>>>(
        q_w, in_b, out_w, out_b, w_hh, b_hh, ln_g, ln_b2,
        gK, gV, gXp, gH, gC, gHln, gQ, gSc, gCtx, gO, gHall, attnb);

    // ---- batched logits: [B*S, V] = gHall @ lin_w^T + lin_b ----
    gemm128<<<dim3(V_ / 128, (B_ * S_) / 128), 256>>>(
        gHall, H_, lin_w, lin_b, preds, V_, H_);
}

// round 4
// speedup vs baseline: 2.5216x; 1.0784x over previous
#include <cuda_runtime.h>
#include <math.h>
#include <float.h>

#define B_   32
#define NF_  196
#define ENC_ 2048
#define V_   32000
#define ED_  512
#define S_   32
#define H_   1024
#define NB_  128        // persistent grid size (all co-resident on 148 SMs)

// ---------------- f32x2 packed helpers (sm_103a) -----------------------------
__device__ __forceinline__ void fma2(unsigned long long& d,
                                     unsigned long long a, unsigned long long b) {
    asm("fma.rn.f32x2 %0, %1, %2, %0;" : "+l"(d) : "l"(a), "l"(b));
}
__device__ __forceinline__ unsigned long long pack2(float lo, float hi) {
    unsigned long long r;
    asm("mov.b64 %0, {%1, %2};" : "=l"(r) : "f"(lo), "f"(hi));
    return r;
}
__device__ __forceinline__ float2 unpk2(unsigned long long v) {
    float2 r;
    asm("mov.b64 {%0, %1}, %2;" : "=f"(r.x), "=f"(r.y) : "l"(v));
    return r;
}

// ---------------- scratch (single __device__ array; no allocations) ---------
static constexpr size_t SZ_K    = (size_t)B_ * NF_ * H_;
static constexpr size_t OFF_K   = 0;
static constexpr size_t OFF_V   = OFF_K + SZ_K;
static constexpr size_t OFF_MEAN= OFF_V + SZ_K;
static constexpr size_t OFF_H   = OFF_MEAN + (size_t)B_ * ENC_;
static constexpr size_t OFF_C   = OFF_H   + (size_t)B_ * H_;
static constexpr size_t OFF_HLN = OFF_C   + (size_t)B_ * H_;
static constexpr size_t OFF_Q   = OFF_HLN + (size_t)B_ * H_;
static constexpr size_t OFF_CTX = OFF_Q   + (size_t)B_ * H_;
static constexpr size_t OFF_O   = OFF_CTX + (size_t)B_ * H_;
static constexpr size_t OFF_EMB = OFF_O   + (size_t)B_ * H_;
static constexpr size_t OFF_XP  = OFF_EMB + (size_t)B_ * S_ * ED_;
static constexpr size_t OFF_HALL= OFF_XP  + (size_t)B_ * S_ * 4 * H_;
static constexpr size_t OFF_AD  = OFF_HALL+ (size_t)B_ * S_ * H_;
static constexpr size_t TOTAL_F = OFF_AD  + (size_t)B_ * S_ * NF_;

__device__ float g_scratch[TOTAL_F];
__device__ unsigned g_bar_count = 0;
__device__ unsigned g_bar_gen   = 0;

// ---------------- grid-wide barrier (all NB_ blocks resident) ----------------
__device__ __forceinline__ void grid_bar() {
    __syncthreads();
    if (threadIdx.x == 0) {
        __threadfence();
        unsigned gen = *(volatile unsigned*)&g_bar_gen;
        unsigned a = atomicAdd(&g_bar_count, 1u);
        if (a == NB_ - 1) {
            atomicExch(&g_bar_count, 0u);
            __threadfence();
            atomicAdd(&g_bar_gen, 1u);
        } else {
            while (*(volatile unsigned*)&g_bar_gen == gen) { }
        }
        __threadfence();
    }
    __syncthreads();
}

// ---------------- mean over N + exact gelu ----------------------------------
__global__ __launch_bounds__(256) void mean_gelu_kernel(
    const float* __restrict__ feat, float* __restrict__ outMean)
{
    int b = blockIdx.y;
    int e = blockIdx.x * 256 + threadIdx.x;
    const float* p = feat + (size_t)b * NF_ * ENC_ + e;
    float s = 0.f;
    #pragma unroll 4
    for (int n = 0; n < NF_; n++) s += p[(size_t)n * ENC_];
    s *= (1.0f / (float)NF_);
    outMean[(size_t)b * ENC_ + e] = 0.5f * s * (1.0f + erff(s * 0.70710678118654752f));
}

// ---------------- embedding gather -------------------------------------------
__global__ __launch_bounds__(256) void gather_kernel(
    const float* __restrict__ emb, const int* __restrict__ cap,
    float* __restrict__ out)
{
    int idx = blockIdx.x * 256 + threadIdx.x;
    int d  = idx & (ED_ - 1);
    int bs = idx >> 9;
    out[idx] = emb[(size_t)cap[bs] * ED_ + d];
}

// ---------------- batched GEMV for M=32 (setup h0/c0 only) -------------------
__global__ __launch_bounds__(256) void gemvM32(
    const float* __restrict__ A, const float* __restrict__ W,
    const float* __restrict__ bias, float* __restrict__ C, int ldc, int K)
{
    __shared__ float sA[32][64];
    int tid = threadIdx.x, lane = tid & 31, w = tid >> 5;
    int n = blockIdx.x * 8 + w;
    const float* Wn = W + (size_t)n * K;
    float acc[32];
    #pragma unroll
    for (int b = 0; b < 32; b++) acc[b] = 0.f;
    for (int k0 = 0; k0 < K; k0 += 64) {
        __syncthreads();
        int kk = tid & 63, bb = tid >> 6;
        #pragma unroll
        for (int i = 0; i < 8; i++)
            sA[bb + i * 4][kk] = A[(size_t)(bb + i * 4) * K + k0 + kk];
        __syncthreads();
        float w0 = Wn[k0 + lane], w1 = Wn[k0 + 32 + lane];
        #pragma unroll
        for (int b = 0; b < 32; b++)
            acc[b] += w0 * sA[b][lane] + w1 * sA[b][lane + 32];
    }
    float out = 0.f;
    #pragma unroll
    for (int b = 0; b < 32; b++) {
        float v = acc[b];
        #pragma unroll
        for (int o = 16; o; o >>= 1) v += __shfl_xor_sync(0xffffffffu, v, o);
        if (lane == b) out = v;
    }
    C[(size_t)lane * (size_t)ldc + n] = out + bias[n];
}

// ---------------- 128x128 SGEMM with fma.rn.f32x2: C = A@W^T + bias ----------
__global__ __launch_bounds__(256, 2) void gemm128(
    const float* __restrict__ A, int lda,
    const float* __restrict__ W,          // [N,K]
    const float* __restrict__ bias,
    float* __restrict__ C, int ldc, int K)
{
    __shared__ float sA[16][132];
    __shared__ float sB[16][132];
    int tid = threadIdx.x;
    int m0 = blockIdx.y * 128, n0 = blockIdx.x * 128;
    int lr = tid >> 2;                 // 0..63
    int lk = (tid & 3) * 4;            // 0,4,8,12
    const float* Ab = A + (size_t)m0 * lda + lk;
    const float* Wb = W + (size_t)n0 * K + lk;
    int tx = tid & 15, ty = tid >> 4;

    unsigned long long acc2[8][4];
    #pragma unroll
    for (int i = 0; i < 8; i++)
        #pragma unroll
        for (int j = 0; j < 4; j++) acc2[i][j] = 0ull;

    for (int k0 = 0; k0 < K; k0 += 16) {
        float4 a0 = *(const float4*)(Ab + (size_t)lr * lda + k0);
        float4 a1 = *(const float4*)(Ab + (size_t)(lr + 64) * lda + k0);
        float4 b0 = *(const float4*)(Wb + (size_t)lr * K + k0);
        float4 b1 = *(const float4*)(Wb + (size_t)(lr + 64) * K + k0);
        __syncthreads();
        sA[lk+0][lr]=a0.x; sA[lk+1][lr]=a0.y; sA[lk+2][lr]=a0.z; sA[lk+3][lr]=a0.w;
        sA[lk+0][lr+64]=a1.x; sA[lk+1][lr+64]=a1.y; sA[lk+2][lr+64]=a1.z; sA[lk+3][lr+64]=a1.w;
        sB[lk+0][lr]=b0.x; sB[lk+1][lr]=b0.y; sB[lk+2][lr]=b0.z; sB[lk+3][lr]=b0.w;
        sB[lk+0][lr+64]=b1.x; sB[lk+1][lr+64]=b1.y; sB[lk+2][lr+64]=b1.z; sB[lk+3][lr+64]=b1.w;
        __syncthreads();
        #pragma unroll
        for (int k = 0; k < 16; k++) {
            float ar[8];
            *(float4*)&ar[0] = *(const float4*)&sA[k][ty * 8];
            *(float4*)&ar[4] = *(const float4*)&sA[k][ty * 8 + 4];
            const unsigned long long* pb =
                (const unsigned long long*)&sB[k][tx * 8];
            unsigned long long bb0 = pb[0], bb1 = pb[1], bb2 = pb[2], bb3 = pb[3];
            #pragma unroll
            for (int i = 0; i < 8; i++) {
                unsigned long long aa = pack2(ar[i], ar[i]);
                fma2(acc2[i][0], aa, bb0);
                fma2(acc2[i][1], aa, bb1);
                fma2(acc2[i][2], aa, bb2);
                fma2(acc2[i][3], aa, bb3);
            }
        }
    }

    int n = n0 + tx * 8;
    float bb[8] = {0.f,0.f,0.f,0.f,0.f,0.f,0.f,0.f};
    if (bias) {
        *(float4*)&bb[0] = *(const float4*)(bias + n);
        *(float4*)&bb[4] = *(const float4*)(bias + n + 4);
    }
    #pragma unroll
    for (int i = 0; i < 8; i++) {
        size_t m = (size_t)(m0 + ty * 8 + i);
        float2 v0 = unpk2(acc2[i][0]);
        float2 v1 = unpk2(acc2[i][1]);
        float2 v2 = unpk2(acc2[i][2]);
        float2 v3 = unpk2(acc2[i][3]);
        float4 r0 = make_float4(v0.x+bb[0], v0.y+bb[1], v1.x+bb[2], v1.y+bb[3]);
        float4 r1 = make_float4(v2.x+bb[4], v2.y+bb[5], v3.x+bb[6], v3.y+bb[7]);
        *(float4*)(C + m * (size_t)ldc + n)     = r0;
        *(float4*)(C + m * (size_t)ldc + n + 4) = r1;
    }
}

// ---------------- persistent recurrence kernel -------------------------------
// Dynamic smem layout (floats):
//   SQW  [8192]   q_w rows   [bx*8 .. bx*8+8)
//   SOW  [8192]   out_w rows [bx*8 .. bx*8+8)
//   SWH  [32768]  w_hh rows  {g*1024 + bx*8 + jj}  -> [g][jj][k]
//   SST  [2048]   staging (32 x 64) / LN buffer / q buffer
extern __shared__ float dsm[];

__device__ __forceinline__ void gemv_sm(
    const float* __restrict__ A,       // [32,1024] global
    const float* sW,                   // 8 cols x 1024 in smem
    const float* __restrict__ bias,
    float* __restrict__ C, float* SST, int bx, int tid)
{
    int lane = tid & 31, w = tid >> 5;
    const float* Wn = sW + w * H_;
    unsigned long long acc2[32];
    #pragma unroll
    for (int b = 0; b < 32; b++) acc2[b] = 0ull;

    int cs = (tid & 15) * 4;
    int rs = tid >> 4;
    for (int k0 = 0; k0 < H_; k0 += 64) {
        __syncthreads();
        float4 v0 = *(const float4*)(A + (size_t)rs * H_ + k0 + cs);
        float4 v1 = *(const float4*)(A + (size_t)(rs + 16) * H_ + k0 + cs);
        *(float4*)&SST[rs * 64 + cs] = v0;
        *(float4*)&SST[(rs + 16) * 64 + cs] = v1;
        __syncthreads();
        unsigned long long wp = *(const unsigned long long*)(Wn + k0 + 2 * lane);
        #pragma unroll
        for (int b = 0; b < 32; b++) {
            unsigned long long xp = *(const unsigned long long*)&SST[b * 64 + 2 * lane];
            fma2(acc2[b], wp, xp);
        }
    }
    int n = bx * 8 + w;
    float outv = 0.f;
    #pragma unroll
    for (int b = 0; b < 32; b++) {
        float2 v = unpk2(acc2[b]);
        float s = v.x + v.y;
        #pragma unroll
        for (int o = 16; o; o >>= 1) s += __shfl_xor_sync(0xffffffffu, s, o);
        if (lane == b) outv = s;
    }
    C[(size_t)lane * H_ + n] = outv + bias[n];
}

__global__ __launch_bounds__(256, 1) void recurrence_kernel(
    const float* __restrict__ q_w,  const float* __restrict__ in_b,
    const float* __restrict__ out_w,const float* __restrict__ out_b,
    const float* __restrict__ w_hh, const float* __restrict__ b_hh,
    const float* __restrict__ ln_g, const float* __restrict__ ln_b2,
    const float* __restrict__ gK,   const float* __restrict__ gV,
    const float* __restrict__ gXp,
    float* gH, float* gC, float* gHln, float* gQ,
    float* gCtx, float* gO, float* gHall, float* attnb)
{
    __shared__ float sScore[224];
    __shared__ float sProb[224];
    __shared__ float sred[8];
    __shared__ float sbc;
    __shared__ float sG[1024];         // gates staging [g][jj][b]

    float* SQW = dsm;
    float* SOW = dsm + 8192;
    float* SWH = dsm + 16384;
    float* SST = dsm + 49152;

    int tid = threadIdx.x, lane = tid & 31, w = tid >> 5;
    int bx = blockIdx.x;

    // ---- one-time weight preload into smem ----
    for (int i = tid; i < 8192; i += 256) {
        SQW[i] = q_w [(size_t)bx * 8192 + i];
        SOW[i] = out_w[(size_t)bx * 8192 + i];
    }
    #pragma unroll
    for (int g = 0; g < 4; g++)
        for (int i = tid; i < 8192; i += 256)
            SWH[g * 8192 + i] = w_hh[((size_t)g * H_ + bx * 8) * H_ + i];
    __syncthreads();

    for (int t = 0; t < S_; t++) {
        // ---- P0: q = h @ q_w^T + in_b[:H] ----
        gemv_sm(gH, SQW, in_b, gQ, SST, bx, tid);
        grid_bar();

        // ---- P1: fused scores + softmax + ctx (blocks 0..31, b = bx) ----
        if (bx < 32) {
            int b = bx;
            for (int i = tid; i < 256; i += 256)
                *(float4*)&SST[i * 4] = *(const float4*)(gQ + b * H_ + i * 4);
            __syncthreads();
            // scores
            for (int n = w; n < NF_; n += 8) {
                const float4* kp4 = (const float4*)(gK + ((size_t)b * NF_ + n) * H_);
                float s = 0.f;
                #pragma unroll
                for (int i = 0; i < 8; i++) {
                    int j = lane + 32 * i;
                    float4 k4 = kp4[j];
                    float4 q4 = *(const float4*)&SST[j * 4];
                    s += k4.x*q4.x + k4.y*q4.y + k4.z*q4.z + k4.w*q4.w;
                }
                #pragma unroll
                for (int o = 16; o; o >>= 1) s += __shfl_xor_sync(0xffffffffu, s, o);
                if (lane == 0) sScore[n] = s * 0.03125f;
            }
            __syncthreads();
            // softmax over 196
            float v = (tid < NF_) ? sScore[tid] : -FLT_MAX;
            float m = v;
            #pragma unroll
            for (int o = 16; o; o >>= 1) m = fmaxf(m, __shfl_xor_sync(0xffffffffu, m, o));
            if (lane == 0) sred[w] = m;
            __syncthreads();
            if (tid == 0) {
                float mm = sred[0];
                #pragma unroll
                for (int i = 1; i < 8; i++) mm = fmaxf(mm, sred[i]);
                sbc = mm;
            }
            __syncthreads();
            float e = (tid < NF_) ? expf(v - sbc) : 0.f;
            float s2 = e;
            #pragma unroll
            for (int o = 16; o; o >>= 1) s2 += __shfl_xor_sync(0xffffffffu, s2, o);
            if (lane == 0) sred[w] = s2;
            __syncthreads();
            if (tid == 0) {
                float ss = 0.f;
                #pragma unroll
                for (int i = 0; i < 8; i++) ss += sred[i];
                sbc = ss;
            }
            __syncthreads();
            float p = e / sbc;
            if (tid < NF_) {
                sProb[tid] = p;
                attnb[((size_t)b * S_ + t) * NF_ + tid] = p;
            }
            __syncthreads();
            // ctx = attn @ V  (each thread: 4 consecutive h-cols)
            {
                const float* vb = gV + (size_t)b * NF_ * H_ + tid * 4;
                float4 a = make_float4(0.f, 0.f, 0.f, 0.f);
                #pragma unroll 4
                for (int n = 0; n < NF_; n++) {
                    float pp = sProb[n];
                    float4 v4 = *(const float4*)(vb + (size_t)n * H_);
                    a.x += pp * v4.x; a.y += pp * v4.y;
                    a.z += pp * v4.z; a.w += pp * v4.w;
                }
                *(float4*)(gCtx + b * H_ + tid * 4) = a;
            }
        }
        grid_bar();

        // ---- P3: o = ctx @ out_w^T + out_b ----
        gemv_sm(gCtx, SOW, out_b, gO, SST, bx, tid);
        grid_bar();

        // ---- P4: hln = LN(h + o) (blocks 0..31) ----
        if (bx < 32) {
            int b = bx;
            float loc = 0.f;
            for (int i = tid; i < H_; i += 256) {
                float x = gH[b * H_ + i] + gO[b * H_ + i];
                SST[i] = x;
                loc += x;
            }
            #pragma unroll
            for (int o = 16; o; o >>= 1) loc += __shfl_xor_sync(0xffffffffu, loc, o);
            if (lane == 0) sred[w] = loc;
            __syncthreads();
            if (tid == 0) {
                float s = 0.f;
                #pragma unroll
                for (int i = 0; i < 8; i++) s += sred[i];
                sbc = s * (1.0f / H_);
            }
            __syncthreads();
            float mu = sbc, loc2 = 0.f;
            for (int i = tid; i < H_; i += 256) {
                float d = SST[i] - mu;
                loc2 += d * d;
            }
            #pragma unroll
            for (int o = 16; o; o >>= 1) loc2 += __shfl_xor_sync(0xffffffffu, loc2, o);
            if (lane == 0) sred[w] = loc2;
            __syncthreads();
            if (tid == 0) {
                float s = 0.f;
                #pragma unroll
                for (int i = 0; i < 8; i++) s += sred[i];
                sbc = rsqrtf(s * (1.0f / H_) + 1e-5f);
            }
            __syncthreads();
            float rs = sbc, mu2 = mu;
            for (int i = tid; i < H_; i += 256)
                gHln[b * H_ + i] = (SST[i] - mu2) * rs * ln_g[i] + ln_b2[i];
        }
        grid_bar();

        // ---- P5: gates (smem w_hh) + LSTM pointwise ----
        {
            int j = bx * 8 + w;
            int cs = (tid & 15) * 4;
            int rs = tid >> 4;
            for (int gp = 0; gp < 4; gp += 2) {
                const float* W0 = SWH + (size_t)gp * 8192 + w * H_;
                const float* W1 = SWH + (size_t)(gp + 1) * 8192 + w * H_;
                unsigned long long aA[32], aB[32];
                #pragma unroll
                for (int b = 0; b < 32; b++) { aA[b] = 0ull; aB[b] = 0ull; }
                for (int k0 = 0; k0 < H_; k0 += 64) {
                    __syncthreads();
                    float4 v0 = *(const float4*)(gHln + (size_t)rs * H_ + k0 + cs);
                    float4 v1 = *(const float4*)(gHln + (size_t)(rs + 16) * H_ + k0 + cs);
                    *(float4*)&SST[rs * 64 + cs] = v0;
                    *(float4*)&SST[(rs + 16) * 64 + cs] = v1;
                    __syncthreads();
                    unsigned long long w0 = *(const unsigned long long*)(W0 + k0 + 2 * lane);
                    unsigned long long w1 = *(const unsigned long long*)(W1 + k0 + 2 * lane);
                    #pragma unroll
                    for (int b = 0; b < 32; b++) {
                        unsigned long long xp =
                            *(const unsigned long long*)&SST[b * 64 + 2 * lane];
                        fma2(aA[b], w0, xp);
                        fma2(aB[b], w1, xp);
                    }
                }
                float outA = 0.f, outB = 0.f;
                #pragma unroll
                for (int b = 0; b < 32; b++) {
                    float2 va = unpk2(aA[b]);
                    float2 vb = unpk2(aB[b]);
                    float sa = va.x + va.y, sb2 = vb.x + vb.y;
                    #pragma unroll
                    for (int o = 16; o; o >>= 1) {
                        sa  += __shfl_xor_sync(0xffffffffu, sa,  o);
                        sb2 += __shfl_xor_sync(0xffffffffu, sb2, o);
                    }
                    if (lane == b) { outA = sa; outB = sb2; }
                }
                int nA = gp * H_ + j, nB = (gp + 1) * H_ + j;
                size_t xrow = ((size_t)lane * S_ + t) * (4 * H_);
                outA += b_hh[nA] + gXp[xrow + nA];
                outB += b_hh[nB] + gXp[xrow + nB];
                sG[gp * 256 + w * 32 + lane]       = outA;
                sG[(gp + 1) * 256 + w * 32 + lane] = outB;
            }
            __syncthreads();
            int b = tid & 31, jj = tid >> 5;
            int j2 = bx * 8 + jj;
            float ii = sG[0 * 256 + jj * 32 + b];
            float ff = sG[1 * 256 + jj * 32 + b];
            float gg = sG[2 * 256 + jj * 32 + b];
            float oo = sG[3 * 256 + jj * 32 + b];
            float si = 1.f / (1.f + expf(-ii));
            float sf = 1.f / (1.f + expf(-ff));
            float so = 1.f / (1.f + expf(-oo));
            float cn = sf * gC[b * H_ + j2] + si * tanhf(gg);
            float hn = so * tanhf(cn);
            gC[b * H_ + j2] = cn;
            gH[b * H_ + j2] = hn;
            gHall[((size_t)b * S_ + t) * H_ + j2] = hn;
        }
        grid_bar();
    }
}

// ---------------- orchestration ----------------------------------------------
extern "C" void kernel_launch(void* const* d_in, const int* in_sizes, int n_in,
                              void* d_out, int out_size)
{
    const float* features = (const float*)d_in[0];
    const int*   captions = (const int*)  d_in[1];
    const float* emb      = (const float*)d_in[2];
    const float* q_w      = (const float*)d_in[3];
    const float* k_w      = (const float*)d_in[4];
    const float* v_w      = (const float*)d_in[5];
    const float* in_b     = (const float*)d_in[6];
    const float* out_w    = (const float*)d_in[7];
    const float* out_b    = (const float*)d_in[8];
    const float* h0_w     = (const float*)d_in[9];
    const float* h0_b     = (const float*)d_in[10];
    const float* c0_w     = (const float*)d_in[11];
    const float* c0_b     = (const float*)d_in[12];
    const float* w_ih     = (const float*)d_in[13];
    const float* b_ih     = (const float*)d_in[14];
    const float* w_hh     = (const float*)d_in[15];
    const float* b_hh     = (const float*)d_in[16];
    const float* ln_g     = (const float*)d_in[17];
    const float* ln_b2    = (const float*)d_in[18];
    const float* lin_w    = (const float*)d_in[19];
    const float* lin_b    = (const float*)d_in[20];

    float* sc = nullptr;
    cudaGetSymbolAddress((void**)&sc, g_scratch);
    float* gK    = sc + OFF_K;
    float* gV    = sc + OFF_V;
    float* gMean = sc + OFF_MEAN;
    float* gH    = sc + OFF_H;
    float* gC    = sc + OFF_C;
    float* gHln  = sc + OFF_HLN;
    float* gQ    = sc + OFF_Q;
    float* gCtx  = sc + OFF_CTX;
    float* gO    = sc + OFF_O;
    float* gEmb  = sc + OFF_EMB;
    float* gXp   = sc + OFF_XP;
    float* gHall = sc + OFF_HALL;
    float* gAd   = sc + OFF_AD;

    float* out   = (float*)d_out;
    float* preds = out;
    const size_t PRED = (size_t)B_ * S_ * V_;
    bool wa = ((size_t)out_size >= PRED + (size_t)B_ * S_ * NF_);
    float* attnb = wa ? (out + PRED) : gAd;

    const int REC_SMEM = 51200 * 4;   // 200 KB dynamic smem
    cudaFuncSetAttribute(recurrence_kernel,
                         cudaFuncAttributeMaxDynamicSharedMemorySize, REC_SMEM);

    // ---- setup (hoisted out of the recurrence) ----
    mean_gelu_kernel<<<dim3(ENC_ / 256, B_), 256>>>(features, gMean);
    gemvM32<<<H_ / 8, 256>>>(gMean, h0_w, h0_b, gH, H_, ENC_);
    gemvM32<<<H_ / 8, 256>>>(gMean, c0_w, c0_b, gC, H_, ENC_);
    gemm128<<<dim3(H_ / 128, (B_ * NF_) / 128), 256>>>(
        features, ENC_, k_w, in_b + H_,     gK, H_, ENC_);
    gemm128<<<dim3(H_ / 128, (B_ * NF_) / 128), 256>>>(
        features, ENC_, v_w, in_b + 2 * H_, gV, H_, ENC_);
    gather_kernel<<<(B_ * S_ * ED_) / 256, 256>>>(emb, captions, gEmb);
    gemm128<<<dim3((4 * H_) / 128, (B_ * S_) / 128), 256>>>(
        gEmb, ED_, w_ih, b_ih, gXp, 4 * H_, ED_);

    // ---- whole recurrence in one persistent kernel ----
    recurrence_kernel<<<NB_, 256, REC_SMEM>>>(
        q_w, in_b, out_w, out_b, w_hh, b_hh, ln_g, ln_b2,
        gK, gV, gXp, gH, gC, gHln, gQ, gCtx, gO, gHall, attnb);

    // ---- batched logits: [B*S, V] = gHall @ lin_w^T + lin_b ----
    gemm128<<<dim3(V_ / 128, (B_ * S_) / 128), 256>>>(
        gHall, H_, lin_w, lin_b, preds, V_, H_);
}